// round 6
// baseline (speedup 1.0000x reference)
#include <cuda_runtime.h>

// 16-qubit, 2-layer BasicEntangler QNN — branchless transfer-matrix closed form.
// Algebra verified rounds 1-5:
//   <Z_{R_w}> = <0| Prod_j exp(i theta_j X_{m_j}) |0>  ->  2-state chain DP,
//   one chain per lane (lane^16 = t15 partner), depth-2 P-product recurrence,
//   shfl combine. This round: float2-packed smem (halve LDS issue count),
//   minimal prologue — we are at the single-kernel launch-overhead floor.

#define NQ 16

__constant__ unsigned int R_MASK[16] = {
    0xAAABu, 0xFFFDu, 0xFFFAu, 0xFFF5u, 0xFFEAu, 0xFFD5u, 0xFFAAu, 0xFF55u,
    0xFEAAu, 0xFD55u, 0xFAAAu, 0xF555u, 0xEAAAu, 0xD555u, 0xAAAAu, 0x5555u
};

__global__ void __launch_bounds__(32)
qnn_tm5(const float* __restrict__ x, const float* __restrict__ wts,
        float* __restrict__ out) {
    __shared__ float2 ph[NQ], th[NQ];   // (cos, sin) packed

    const int lane = threadIdx.x;
    const int w    = lane & 15;          // output wire
    const bool isB = lane >= 16;         // chain select (t15 = 1)
    const int b    = blockIdx.x;         // sample (one warp per sample)

    // prologue: half-warp computes phi sincos, half computes theta sincos
    {
        float s, c;
        if (!isB) {
            __sincosf(x[b * NQ + w] + wts[w], &s, &c);   // phi = x + W0
            ph[w] = make_float2(c, s);
        } else {
            __sincosf(wts[NQ + w], &s, &c);              // layer-1 theta
            th[w] = make_float2(c, s);
        }
    }
    __syncwarp();

    const unsigned S = R_MASK[w];

    // ---- init (step v=0); chain-B v==1 u-swap folded into amp0<->amp1 ----
    float a0x, a0y, a1x, a1y;
    {
        const bool ab = (S ^ (S >> 1)) & 1;              // b_0={0,1}
        const bool ae = S & 1;
        const float2 t0 = th[0], p0 = ph[0];
        const float wt0r = ab ? t0.x : 1.f;
        const float wt1i = ab ? t0.y : 0.f;
        const float wm0r = ae ? p0.x : 1.f;
        const float wm1i = ae ? p0.y : 0.f;
        const float q0 = (isB ? wt1i : wt0r) * wm0r;
        const float q1 = (isB ? wt0r : -wt1i) * wm1i;
        a0x = isB ? 0.f : q0;  a0y = isB ? q0 : 0.f;
        a1x = isB ? 0.f : q1;  a1y = isB ? q1 : 0.f;
    }

    // ---- steps v=1..14: depth-2 recurrence, P = wt (x) wm precomputed ----
#pragma unroll
    for (int v = 1; v <= 14; v++) {
        const bool ab = ((S >> v) ^ (S >> (v + 1))) & 1;
        const bool ae = (S >> v) & 1;
        const float2 tv = th[v], pv = ph[v];
        const float wt0r = ab ? tv.x : 1.f;
        const float wt1i = ab ? tv.y : 0.f;
        const float wm0r = ae ? pv.x : 1.f;
        const float wm1i = ae ? pv.y : 0.f;
        const float P00 = wt0r * wm0r;
        const float P01 = wt0r * wm1i;
        const float P10 = wt1i * wm0r;
        const float P11 = wt1i * wm1i;
        const float n0x =  P00 * a0x - P01 * a1y;
        const float n0y =  P00 * a0y + P01 * a1x;
        const float n1x = -P10 * a1y - P11 * a0x;
        const float n1y =  P10 * a1x - P11 * a0y;
        a0x = n0x; a0y = n0y; a1x = n1x; a1y = n1y;
    }

    // ---- close (mask bit 15), per-chain component select ----
    float val;
    {
        const bool ae = (S >> 15) & 1;
        const float2 p15 = ph[15];
        const float wm0r = ae ? p15.x : 1.f;
        const float wm1i = ae ? p15.y : 0.f;
        const float r0 = isB ? wm1i : wm0r;
        const float r1 = isB ? wm0r : -wm1i;
        val = a0x * r0 + a1y * r1;       // A: resAx ; B: resBy
    }

    // combine chains: lane<16 holds A, partner lane^16 holds B
    const float other = __shfl_xor_sync(0xFFFFFFFFu, val, 16);
    if (!isB) {
        const bool ab15 = (S ^ (S >> 1) ^ (S >> 15)) & 1;   // b_15={0,1,15}
        const float2 t15 = th[15];
        const float w150r = ab15 ? t15.x : 1.f;
        const float w151i = ab15 ? t15.y : 0.f;
        out[b * NQ + w] = w150r * val - w151i * other;
    }
}

extern "C" void kernel_launch(void* const* d_in, const int* in_sizes, int n_in,
                              void* d_out, int out_size) {
    const float* x   = (const float*)d_in[0];   // (32,16)
    const float* wts = (const float*)d_in[1];   // (2,16)
    if (n_in >= 2 && in_sizes[0] == 32 && in_sizes[1] == 512) {
        const float* tmp = x; x = wts; wts = tmp;  // defensive order swap
    }
    float* out = (float*)d_out;                 // (32,16) float32

    qnn_tm5<<<32, 32>>>(x, wts, out);
}